// round 15
// baseline (speedup 1.0000x reference)
#include <cuda_runtime.h>
#include <cuda_fp16.h>
#include <math.h>
#include <stdint.h>

#define BSZ 512
#define INPD 512
#define CD 1024
#define ND 256
#define DD 128
#define HH 8

// ---------------- scratch (single device global, no allocations) ----------
#define GATES_OFF 0
#define HEADS_OFF 2097152
#define BR_OFF    4194304
#define BW_OFF    4198400
#define SH_OFF    4202496
#define GA_OFF    4214784
#define FP16_OFF  4218880
#define SCRATCH_TOTAL 17195008   // floats (~69MB)

// fp16 area offsets (in halves)
#define WCAT1_H 0u            // [4096][2560]  = [Wih1|Whh1]
#define WCAT2_H 10485760u     // [4096][2048]  = [Wih2|Whh2]
#define WHD_H   18874368u     // [4096][1024]  = Wrk|Wwk|Wer|Wad stacked
#define ACAT1_H 23068672u     // [512][2560]   = [x|r_prev|h1]
#define ACAT2_H 24379392u     // [512][2048]   = [h1n|h2]
#define H2NH    25427968u     // [512][1024]   = h2n

__device__ __align__(16) float g_scratch[SCRATCH_TOTAL];

__device__ __forceinline__ float sigf(float x){ return __fdividef(1.f, 1.f + __expf(-x)); }
__device__ __forceinline__ float tanhfast(float x){
    float e = __expf(2.f*x);
    return 1.f - __fdividef(2.f, e + 1.f);
}
__device__ __forceinline__ float softplusf_(float x){ return x>20.f ? x : log1pf(expf(x)); }

// ---------------- batched f32 -> f16 conversion with row remap --------------
struct CvtSeg { const float* src; __half* dst; int cpr, drc, doff; };
struct CvtCfg { CvtSeg s[12]; int off[13]; int total8; };

__global__ void cvt_f2h(CvtCfg cfg)
{
    int i = blockIdx.x*blockDim.x + threadIdx.x;
    if (i >= cfg.total8) return;
    int lo = 0;
    #pragma unroll
    for (int k=1;k<=12;k++) if (i >= cfg.off[k]) lo = k;
    int j = i - cfg.off[lo];
    const float* src = cfg.s[lo].src;
    __half* dst = cfg.s[lo].dst;
    int cpr = cfg.s[lo].cpr, drc = cfg.s[lo].drc, doff = cfg.s[lo].doff;
    int row = j / cpr;
    int col = j - row*cpr;
    size_t dchunk = (size_t)row*drc + doff + col;
    const float4* sp = (const float4*)src + 2*(size_t)j;
    float4 u = sp[0], v = sp[1];
    __half2 h0 = __floats2half2_rn(u.x,u.y), h1 = __floats2half2_rn(u.z,u.w);
    __half2 h2 = __floats2half2_rn(v.x,v.y), h3 = __floats2half2_rn(v.z,v.w);
    uint4 o;
    o.x = *(uint32_t*)&h0; o.y = *(uint32_t*)&h1;
    o.z = *(uint32_t*)&h2; o.w = *(uint32_t*)&h3;
    *((uint4*)(dst + 8*dchunk)) = o;
}

// =====================  fp16 tensor-core GEMM (cp.async, 3-stage, BK=64) ====
// C[M,N] = A[M,K] @ W[N,K]^T + bias (+bias2)
// BM=128, BN=64, BK=64 halves. 512 threads, 16 warps (4m x 4n), warp 32x16.
// smem rows are 32 words (64 halves); chunk swizzle: chunk ^ (row&7).

__device__ __forceinline__ void issue_stage(const __half* A, int lda,
                                            const __half* W, int ldw,
                                            int bm, int bn, int t, int k0,
                                            uint32_t aBase, uint32_t bBase)
{
    const int r0 = t>>3, ch = t&7;   // 64 row-groups x 8 chunks
    {
        const __half* a = A + (size_t)(bm+r0)*lda + k0 + ch*8;
        uint32_t d = aBase + 4*((r0<<5) + ((ch ^ (r0&7))<<2));
        asm volatile("cp.async.cg.shared.global [%0], [%1], 16;\n" :: "r"(d), "l"(a) : "memory");
    }
    {
        int row = r0 + 64;
        const __half* a = A + (size_t)(bm+row)*lda + k0 + ch*8;
        uint32_t d = aBase + 4*((row<<5) + ((ch ^ (row&7))<<2));
        asm volatile("cp.async.cg.shared.global [%0], [%1], 16;\n" :: "r"(d), "l"(a) : "memory");
    }
    {
        const __half* b = W + (size_t)(bn+r0)*ldw + k0 + ch*8;
        uint32_t d = bBase + 4*((r0<<5) + ((ch ^ (r0&7))<<2));
        asm volatile("cp.async.cg.shared.global [%0], [%1], 16;\n" :: "r"(d), "l"(b) : "memory");
    }
}

__device__ __forceinline__ void ldm_x4(uint32_t& r0, uint32_t& r1, uint32_t& r2, uint32_t& r3,
                                       uint32_t addr){
    asm volatile("ldmatrix.sync.aligned.m8n8.x4.shared.b16 {%0,%1,%2,%3}, [%4];"
        : "=r"(r0), "=r"(r1), "=r"(r2), "=r"(r3) : "r"(addr));
}

// smem layout (bytes): A stages 3x16384 @0, B stages 3x8192 @49152. total 73728.
__global__ void __launch_bounds__(512,2) gemm_f16(
    const __half* __restrict__ A, int lda,
    const __half* __restrict__ W, int ldw, int S,     // S = K/64 stages
    const float* __restrict__ b0, const float* __restrict__ b1,
    const float* __restrict__ b2, const float* __restrict__ b3,
    const float* __restrict__ e0, const float* __restrict__ e1,
    const float* __restrict__ e2, const float* __restrict__ e3,
    int has2, float* __restrict__ C, int ldc)
{
    extern __shared__ __align__(16) uint32_t sm[];
    const int tid = threadIdx.x;
    const int wid = tid>>5, lane = tid&31;
    const int bm = blockIdx.y*128, bn = blockIdx.x*64;
    const int wm = (wid&3)*32, wn = (wid>>2)*16;
    const int g = lane>>2, tig = lane&3;
    const int grp = lane>>3, rowin = lane&7;

    const uint32_t smBase = (uint32_t)__cvta_generic_to_shared(&sm[0]);

    float acc[2][2][4];
    #pragma unroll
    for (int i=0;i<2;i++)
        #pragma unroll
        for (int j=0;j<2;j++)
            #pragma unroll
            for (int t=0;t<4;t++) acc[i][j][t]=0.f;

    issue_stage(A, lda, W, ldw, bm, bn, tid, 0,  smBase,         smBase+49152);
    asm volatile("cp.async.commit_group;\n" ::: "memory");
    issue_stage(A, lda, W, ldw, bm, bn, tid, 64, smBase+16384,   smBase+49152+8192);
    asm volatile("cp.async.commit_group;\n" ::: "memory");

    for (int s = 0; s < S; s++){
        if (s+1 < S) asm volatile("cp.async.wait_group 1;\n" ::: "memory");
        else         asm volatile("cp.async.wait_group 0;\n" ::: "memory");
        __syncthreads();

        if (s+2 < S){
            int b2i = (s+2)%3;
            issue_stage(A, lda, W, ldw, bm, bn, tid, (s+2)*64,
                        smBase + b2i*16384, smBase + 49152 + b2i*8192);
            asm volatile("cp.async.commit_group;\n" ::: "memory");
        }

        const int buf = s%3;
        const uint32_t aBase = smBase + buf*16384;
        const uint32_t bBase = smBase + 49152 + buf*8192;

        #pragma unroll
        for (int kk=0;kk<4;kk++){
            uint32_t af[2][4], bf[4];
            #pragma unroll
            for (int mf=0;mf<2;mf++){
                int arow  = wm + mf*16 + ((grp&1)<<3) + rowin;
                int achunk = kk*2 + (grp>>1);
                uint32_t aw = (arow<<5) + ((achunk ^ (arow&7))<<2);
                ldm_x4(af[mf][0], af[mf][1], af[mf][2], af[mf][3], aBase + 4*aw);
            }
            {
                int brow  = wn + ((grp>>1)<<3) + rowin;
                int bchunk = kk*2 + (grp&1);
                uint32_t bw = (brow<<5) + ((bchunk ^ (brow&7))<<2);
                ldm_x4(bf[0], bf[1], bf[2], bf[3], bBase + 4*bw);
            }
            #pragma unroll
            for (int mf=0;mf<2;mf++)
                #pragma unroll
                for (int nf=0;nf<2;nf++)
                    asm volatile(
                        "mma.sync.aligned.m16n8k16.row.col.f32.f16.f16.f32 "
                        "{%0,%1,%2,%3},{%4,%5,%6,%7},{%8,%9},{%0,%1,%2,%3};"
                        : "+f"(acc[mf][nf][0]), "+f"(acc[mf][nf][1]),
                          "+f"(acc[mf][nf][2]), "+f"(acc[mf][nf][3])
                        : "r"(af[mf][0]), "r"(af[mf][1]), "r"(af[mf][2]), "r"(af[mf][3]),
                          "r"(bf[nf*2]), "r"(bf[nf*2+1]));
        }
    }

    // epilogue (bias quartered by 1024-col blocks)
    const int q = bn>>10;
    const float* bq = (q==0)?b0:(q==1)?b1:(q==2)?b2:b3;
    const float* eq = (q==0)?e0:(q==1)?e1:(q==2)?e2:e3;
    #pragma unroll
    for (int mf=0;mf<2;mf++){
        int row = bm + wm + mf*16 + g;
        #pragma unroll
        for (int nf=0;nf<2;nf++){
            int col = bn + wn + nf*8 + 2*tig;
            int cq = col & 1023;
            float b0v = bq[cq], b1v = bq[cq+1];
            if (has2){ b0v += eq[cq]; b1v += eq[cq+1]; }
            float2 v0; v0.x = acc[mf][nf][0] + b0v; v0.y = acc[mf][nf][1] + b1v;
            float2 v1; v1.x = acc[mf][nf][2] + b0v; v1.y = acc[mf][nf][3] + b1v;
            *(float2*)&C[(size_t)row*ldc + col]     = v0;
            *(float2*)&C[(size_t)(row+8)*ldc + col] = v1;
        }
    }
}

// ---------------- LSTM pointwise (gate order i,f,g,o) ----------------------
__global__ void lstm_pw(const float* __restrict__ g, const float* __restrict__ cprev,
                        float* __restrict__ hout, float* __restrict__ cout,
                        __half* __restrict__ hout16, int ldh)
{
    int idx = blockIdx.x*blockDim.x + threadIdx.x;
    if (idx >= BSZ*CD) return;
    int bb = idx >> 10, cc = idx & 1023;
    const float* gr = g + (size_t)bb*4096;
    float gi = sigf(gr[cc]);
    float gf = sigf(gr[1024+cc]);
    float gg = tanhfast(gr[2048+cc]);
    float go = sigf(gr[3072+cc]);
    float cn = gf*cprev[idx] + gi*gg;
    cout[idx] = cn;
    float h = go * tanhfast(cn);
    hout[idx] = h;
    hout16[(size_t)bb*ldh + cc] = __float2half(h);
}

// ---------------- fused small heads (fp16 h input) ---------------------------
__global__ void gemv_heads4(const __half* __restrict__ h,
                            const float* __restrict__ Wrb, const float* __restrict__ brb,
                            const float* __restrict__ Wwb, const float* __restrict__ bwb,
                            const float* __restrict__ Wsh, const float* __restrict__ bsh,
                            const float* __restrict__ Wga, const float* __restrict__ bga,
                            float* __restrict__ orb, float* __restrict__ owb,
                            float* __restrict__ osh, float* __restrict__ oga)
{
    int gw = (blockIdx.x*blockDim.x + threadIdx.x) >> 5;
    int lane = threadIdx.x & 31;
    if (gw >= BSZ*48) return;
    int bidx = gw / 48, t = gw - bidx*48;
    const float* W; const float* bias; float* out; int n; int nout;
    if (t < 8)       { W=Wrb; bias=brb; out=orb; n=t;     nout=8;  }
    else if (t < 16) { W=Wwb; bias=bwb; out=owb; n=t-8;   nout=8;  }
    else if (t < 40) { W=Wsh; bias=bsh; out=osh; n=t-16;  nout=24; }
    else             { W=Wga; bias=bga; out=oga; n=t-40;  nout=8;  }
    const uint2* hv = (const uint2*)(h + (size_t)bidx*CD);
    const float4* wv = (const float4*)(W + (size_t)n*CD);
    float s = 0.f;
    #pragma unroll 4
    for (int i=lane; i<CD/4; i+=32){
        uint2 u = hv[i];
        float2 f0 = __half22float2(*(__half2*)&u.x);
        float2 f1 = __half22float2(*(__half2*)&u.y);
        float4 w = wv[i];
        s += f0.x*w.x + f0.y*w.y + f1.x*w.z + f1.y*w.w;
    }
    #pragma unroll
    for (int o=16;o;o>>=1) s += __shfl_xor_sync(0xffffffffu, s, o);
    if (lane==0) out[(size_t)bidx*nout + n] = s + bias[n];
}

// ---------------- write path: content weights + memory update (fused) -------
__global__ void __launch_bounds__(256) write_path(
    const float* __restrict__ Mp,
    const float* __restrict__ Kraw, int ldk,
    const float* __restrict__ braw,
    const float* __restrict__ eraw, const float* __restrict__ araw,
    float* __restrict__ Mo)
{
    int b = blockIdx.x;
    __shared__ __align__(16) float Kn[HH][DD];
    __shared__ float cosm[HH][ND];
    __shared__ float inv[HH];
    __shared__ float er[HH][DD], ad[HH][DD];
    int tid = threadIdx.x, wid = tid>>5, lane = tid&31;

    for (int i=tid; i<HH*DD; i+=256){
        Kn[i>>7][i&127] = Kraw[(size_t)b*ldk + i];
        er[i>>7][i&127] = sigf(eraw[(size_t)b*ldk + i]);
        ad[i>>7][i&127] = tanhfast(araw[(size_t)b*ldk + i]);
    }
    __syncthreads();
    {
        float s=0.f;
        for (int d=lane; d<DD; d+=32){ float v=Kn[wid][d]; s+=v*v; }
        #pragma unroll
        for (int o=16;o;o>>=1) s += __shfl_xor_sync(0xffffffffu, s, o);
        if (lane==0) inv[wid] = 1.f / fmaxf(sqrtf(s), 1e-12f);
    }
    __syncthreads();
    for (int i=tid; i<HH*DD; i+=256) Kn[i>>7][i&127] *= inv[i>>7];
    __syncthreads();

    for (int n = wid; n < ND; n += 8) {
        const float4* Mr = (const float4*)(Mp + ((size_t)b*ND + n)*DD);
        float4 mv = Mr[lane];
        float vals[9];
        vals[8] = mv.x*mv.x + mv.y*mv.y + mv.z*mv.z + mv.w*mv.w;
        #pragma unroll
        for (int h=0;h<HH;h++){
            float4 kv = *(const float4*)&Kn[h][lane*4];
            vals[h] = mv.x*kv.x + mv.y*kv.y + mv.z*kv.z + mv.w*kv.w;
        }
        #pragma unroll
        for (int o=16;o;o>>=1)
            #pragma unroll
            for (int j=0;j<9;j++) vals[j] += __shfl_xor_sync(0xffffffffu, vals[j], o);
        if (lane==0){
            float im = 1.f / fmaxf(sqrtf(vals[8]), 1e-12f);
            #pragma unroll
            for (int h=0;h<HH;h++) cosm[h][n] = vals[h]*im;
        }
    }
    __syncthreads();

    float beta = softplusf_(braw[(size_t)b*HH + wid]);
    float mx = -1e30f;
    #pragma unroll
    for (int k=0;k<8;k++) mx = fmaxf(mx, beta*cosm[wid][lane+32*k]);
    #pragma unroll
    for (int o=16;o;o>>=1) mx = fmaxf(mx, __shfl_xor_sync(0xffffffffu, mx, o));
    float ev[8]; float sum=0.f;
    #pragma unroll
    for (int k=0;k<8;k++){ float e = expf(beta*cosm[wid][lane+32*k]-mx); ev[k]=e; sum+=e; }
    #pragma unroll
    for (int o=16;o;o>>=1) sum += __shfl_xor_sync(0xffffffffu, sum, o);
    float isum = 1.f/sum;
    #pragma unroll
    for (int k=0;k<8;k++) cosm[wid][lane+32*k] = ev[k]*isum;
    __syncthreads();

    int d = tid & 127, half = tid >> 7;
    for (int n = half; n < ND; n += 2){
        size_t off = ((size_t)b*ND + n)*DD + d;
        float mp = Mp[off];
        float es=0.f, as=0.f;
        #pragma unroll
        for (int h=0;h<HH;h++){
            float w = cosm[h][n];
            es += w*er[h][d];
            as += w*ad[h][d];
        }
        Mo[off] = mp*(1.f-es) + as;
    }
}

// ---------------- read path: content + shift + sharpen + r (fused) ----------
__global__ void __launch_bounds__(256) read_path(
    const float* __restrict__ Mm,
    const float* __restrict__ Kraw, int ldk,
    const float* __restrict__ braw,
    const float* __restrict__ shraw,
    const float* __restrict__ garaw,
    float* __restrict__ wout, float* __restrict__ rout)
{
    int b = blockIdx.x;
    __shared__ __align__(16) float Kn[HH][DD];
    __shared__ float cosm[HH][ND];
    __shared__ float inv[HH];
    __shared__ float s3[HH][3];
    __shared__ float part[HH][2][DD];
    int tid = threadIdx.x, wid = tid>>5, lane = tid&31;

    for (int i=tid; i<HH*DD; i+=256)
        Kn[i>>7][i&127] = Kraw[(size_t)b*ldk + i];
    __syncthreads();
    {
        float s=0.f;
        for (int d=lane; d<DD; d+=32){ float v=Kn[wid][d]; s+=v*v; }
        #pragma unroll
        for (int o=16;o;o>>=1) s += __shfl_xor_sync(0xffffffffu, s, o);
        if (lane==0) inv[wid] = 1.f / fmaxf(sqrtf(s), 1e-12f);
    }
    __syncthreads();
    for (int i=tid; i<HH*DD; i+=256) Kn[i>>7][i&127] *= inv[i>>7];
    __syncthreads();

    for (int n = wid; n < ND; n += 8) {
        const float4* Mr = (const float4*)(Mm + ((size_t)b*ND + n)*DD);
        float4 mv = Mr[lane];
        float vals[9];
        vals[8] = mv.x*mv.x + mv.y*mv.y + mv.z*mv.z + mv.w*mv.w;
        #pragma unroll
        for (int h=0;h<HH;h++){
            float4 kv = *(const float4*)&Kn[h][lane*4];
            vals[h] = mv.x*kv.x + mv.y*kv.y + mv.z*kv.z + mv.w*kv.w;
        }
        #pragma unroll
        for (int o=16;o;o>>=1)
            #pragma unroll
            for (int j=0;j<9;j++) vals[j] += __shfl_xor_sync(0xffffffffu, vals[j], o);
        if (lane==0){
            float im = 1.f / fmaxf(sqrtf(vals[8]), 1e-12f);
            #pragma unroll
            for (int h=0;h<HH;h++) cosm[h][n] = vals[h]*im;
        }
    }
    __syncthreads();

    float beta = softplusf_(braw[(size_t)b*HH + wid]);
    float mx = -1e30f;
    #pragma unroll
    for (int k=0;k<8;k++) mx = fmaxf(mx, beta*cosm[wid][lane+32*k]);
    #pragma unroll
    for (int o=16;o;o>>=1) mx = fmaxf(mx, __shfl_xor_sync(0xffffffffu, mx, o));
    float ev[8]; float sum=0.f;
    #pragma unroll
    for (int k=0;k<8;k++){ float e = expf(beta*cosm[wid][lane+32*k]-mx); ev[k]=e; sum+=e; }
    #pragma unroll
    for (int o=16;o;o>>=1) sum += __shfl_xor_sync(0xffffffffu, sum, o);
    float isum = 1.f/sum;
    __syncthreads();
    #pragma unroll
    for (int k=0;k<8;k++) cosm[wid][lane+32*k] = ev[k]*isum;

    if (lane==0){
        const float* sr = shraw + ((size_t)b*HH + wid)*3;
        float a=sr[0], bb2=sr[1], cc=sr[2];
        float m = fmaxf(a, fmaxf(bb2, cc));
        float ea=expf(a-m), eb=expf(bb2-m), ec=expf(cc-m);
        float is = 1.f/(ea+eb+ec);
        s3[wid][0]=ea*is; s3[wid][1]=eb*is; s3[wid][2]=ec*is;
    }
    __syncthreads();

    float sh0 = s3[wid][0], sh1 = s3[wid][1], sh2 = s3[wid][2];
    float gexp = 1.f + softplusf_(garaw[(size_t)b*HH + wid]);
    float wg[8]; float sum2=0.f;
    #pragma unroll
    for (int k=0;k<8;k++){
        int n = lane+32*k;
        float wsv = sh0*cosm[wid][(n+1)&255] + sh1*cosm[wid][n] + sh2*cosm[wid][(n-1)&255];
        float p = powf(wsv, gexp);
        wg[k]=p; sum2+=p;
    }
    #pragma unroll
    for (int o=16;o;o>>=1) sum2 += __shfl_xor_sync(0xffffffffu, sum2, o);
    float inv2 = 1.f/(sum2+1e-12f);
    __syncthreads();
    #pragma unroll
    for (int k=0;k<8;k++){
        float w = wg[k]*inv2;
        cosm[wid][lane+32*k] = w;
        wout[((size_t)b*HH+wid)*ND + lane+32*k] = w;
    }
    __syncthreads();

    int d = tid & 127, half = tid >> 7;
    float accv[HH];
    #pragma unroll
    for (int h=0;h<HH;h++) accv[h]=0.f;
    for (int n = half; n < ND; n += 2){
        float m = Mm[((size_t)b*ND + n)*DD + d];
        #pragma unroll
        for (int h=0;h<HH;h++) accv[h] += cosm[h][n]*m;
    }
    #pragma unroll
    for (int h=0;h<HH;h++) part[h][half][d] = accv[h];
    __syncthreads();
    for (int i=tid; i<HH*DD; i+=256){
        int h = i>>7, dd = i&127;
        rout[((size_t)b*HH+h)*DD + dd] = part[h][0][dd] + part[h][1][dd];
    }
}

// ---------------- launcher ---------------------------------------------------
extern "C" void kernel_launch(void* const* d_in, const int* in_sizes, int n_in,
                              void* d_out, int out_size)
{
    const float* x      = (const float*)d_in[0];
    const float* h1     = (const float*)d_in[1];
    const float* c1     = (const float*)d_in[2];
    const float* h2     = (const float*)d_in[3];
    const float* c2     = (const float*)d_in[4];
    const float* r_prev = (const float*)d_in[6];
    const float* M_prev = (const float*)d_in[7];
    const float* W_ih1  = (const float*)d_in[8];
    const float* W_hh1  = (const float*)d_in[9];
    const float* b_ih1  = (const float*)d_in[10];
    const float* b_hh1  = (const float*)d_in[11];
    const float* W_ih2  = (const float*)d_in[12];
    const float* W_hh2  = (const float*)d_in[13];
    const float* b_ih2  = (const float*)d_in[14];
    const float* b_hh2  = (const float*)d_in[15];
    const float* W_rk   = (const float*)d_in[16];
    const float* b_rk   = (const float*)d_in[17];
    const float* W_wk   = (const float*)d_in[18];
    const float* b_wk   = (const float*)d_in[19];
    const float* W_rb   = (const float*)d_in[20];
    const float* b_rb   = (const float*)d_in[21];
    const float* W_wb   = (const float*)d_in[22];
    const float* b_wb   = (const float*)d_in[23];
    const float* W_er   = (const float*)d_in[24];
    const float* b_er   = (const float*)d_in[25];
    const float* W_ad   = (const float*)d_in[26];
    const float* b_ad   = (const float*)d_in[27];
    const float* W_sh   = (const float*)d_in[28];
    const float* b_sh   = (const float*)d_in[29];
    const float* W_ga   = (const float*)d_in[30];
    const float* b_ga   = (const float*)d_in[31];

    float* out = (float*)d_out;
    const size_t HC = (size_t)BSZ*CD;
    float* h1n = out;
    float* c1n = out + HC;
    float* h2n = out + 2*HC;
    float* c2n = out + 3*HC;
    float* wr  = out + 4*HC;
    float* rr  = wr + (size_t)BSZ*HH*ND;
    float* Mo  = rr + (size_t)BSZ*HH*DD;

    float* S = nullptr;
    cudaGetSymbolAddress((void**)&S, g_scratch);
    float* gates = S + GATES_OFF;
    float* heads = S + HEADS_OFF;
    float* BR    = S + BR_OFF;
    float* BW    = S + BW_OFF;
    float* SHm   = S + SH_OFF;
    float* GA    = S + GA_OFF;
    __half* Hh   = (__half*)(S + FP16_OFF);

    const int DSMEM = 73728;
    cudaFuncSetAttribute(gemm_f16, cudaFuncAttributeMaxDynamicSharedMemorySize, DSMEM);

    // 0) batched f32->f16 conversion + concat gather
    {
        CvtCfg c{};
        struct Row { const float* s; unsigned d; int n8, cpr, drc, doff; };
        const Row rows[12] = {
            { W_ih1, WCAT1_H,            786432, 192, 320, 0   },
            { W_hh1, WCAT1_H,            524288, 128, 320, 192 },
            { W_ih2, WCAT2_H,            524288, 128, 256, 0   },
            { W_hh2, WCAT2_H,            524288, 128, 256, 128 },
            { W_rk,  WHD_H,              131072, 128, 128, 0   },
            { W_wk,  WHD_H + 1048576u,   131072, 128, 128, 0   },
            { W_er,  WHD_H + 2097152u,   131072, 128, 128, 0   },
            { W_ad,  WHD_H + 3145728u,   131072, 128, 128, 0   },
            { x,     ACAT1_H,             32768,  64, 320, 0   },
            { r_prev,ACAT1_H,             65536, 128, 320, 64  },
            { h1,    ACAT1_H,             65536, 128, 320, 192 },
            { h2,    ACAT2_H,             65536, 128, 256, 128 },
        };
        int acc = 0;
        for (int i=0;i<12;i++){
            c.s[i].src = rows[i].s;
            c.s[i].dst = Hh + rows[i].d;
            c.s[i].cpr = rows[i].cpr;
            c.s[i].drc = rows[i].drc;
            c.s[i].doff = rows[i].doff;
            c.off[i] = acc;
            acc += rows[i].n8;
        }
        c.off[12] = acc;
        c.total8 = acc;
        cvt_f2h<<<(c.total8 + 255)/256, 256>>>(c);
    }

    dim3 ggrid(4096/64, BSZ/128);   // 256 CTAs, 512 threads each

    // 1) LSTM1: gates = Acat1 @ Wcat1^T + b_ih1 + b_hh1
    gemm_f16<<<ggrid, 512, DSMEM>>>(Hh+ACAT1_H, 2560, Hh+WCAT1_H, 2560, 2560/64,
        b_ih1, b_ih1+1024, b_ih1+2048, b_ih1+3072,
        b_hh1, b_hh1+1024, b_hh1+2048, b_hh1+3072,
        1, gates, 4096);
    lstm_pw<<<(BSZ*CD + 255)/256, 256>>>(gates, c1, h1n, c1n, Hh+ACAT2_H, 2048);

    // 2) LSTM2
    gemm_f16<<<ggrid, 512, DSMEM>>>(Hh+ACAT2_H, 2048, Hh+WCAT2_H, 2048, 2048/64,
        b_ih2, b_ih2+1024, b_ih2+2048, b_ih2+3072,
        b_hh2, b_hh2+1024, b_hh2+2048, b_hh2+3072,
        1, gates, 4096);
    lstm_pw<<<(BSZ*CD + 255)/256, 256>>>(gates, c2, h2n, c2n, Hh+H2NH, 1024);

    // 3) fused head projections: heads = RK|WK|ER|AD
    gemm_f16<<<ggrid, 512, DSMEM>>>(Hh+H2NH, 1024, Hh+WHD_H, 1024, 1024/64,
        b_rk, b_wk, b_er, b_ad,
        nullptr, nullptr, nullptr, nullptr,
        0, heads, 4096);

    // 4) fused small heads (fp16 h input)
    gemv_heads4<<<(BSZ*48*32 + 255)/256, 256>>>(Hh+H2NH,
        W_rb, b_rb, W_wb, b_wb, W_sh, b_sh, W_ga, b_ga,
        BR, BW, SHm, GA);

    // 5) write path (content weights + memory update, fused)
    write_path<<<BSZ, 256>>>(M_prev, heads + 1024, 4096, BW,
                             heads + 2048, heads + 3072, Mo);

    // 6) read path (content + shift + sharpen + r, fused)
    read_path<<<BSZ, 256>>>(Mo, heads, 4096, BR, SHm, GA, wr, rr);
}

// round 16
// speedup vs baseline: 1.1222x; 1.1222x over previous
#include <cuda_runtime.h>
#include <cuda_fp16.h>
#include <math.h>
#include <stdint.h>

#define BSZ 512
#define INPD 512
#define CD 1024
#define ND 256
#define DD 128
#define HH 8

// ---------------- scratch (single device global, no allocations) ----------
#define GATES_OFF 0
#define HEADS_OFF 2097152
#define BR_OFF    4194304
#define BW_OFF    4198400
#define SH_OFF    4202496
#define GA_OFF    4214784
#define FP16_OFF  4218880
#define SCRATCH_TOTAL 17195008   // floats (~69MB)

// fp16 area offsets (in halves)
#define WCAT1_H 0u            // [4096][2560]  = [Wih1|Whh1]
#define WCAT2_H 10485760u     // [4096][2048]  = [Wih2|Whh2]
#define WHD_H   18874368u     // [4096][1024]  = Wrk|Wwk|Wer|Wad stacked
#define ACAT1_H 23068672u     // [512][2560]   = [x|r_prev|h1]
#define ACAT2_H 24379392u     // [512][2048]   = [h1n|h2]
#define H2NH    25427968u     // [512][1024]   = h2n

__device__ __align__(16) float g_scratch[SCRATCH_TOTAL];

__device__ __forceinline__ float sigf(float x){ return __fdividef(1.f, 1.f + __expf(-x)); }
__device__ __forceinline__ float tanhfast(float x){
    float e = __expf(2.f*x);
    return 1.f - __fdividef(2.f, e + 1.f);
}
__device__ __forceinline__ float softplusf_(float x){ return x>20.f ? x : log1pf(expf(x)); }

// ---------------- batched f32 -> f16 conversion with row remap --------------
struct CvtSeg { const float* src; __half* dst; int cpr, drc, doff; };
struct CvtCfg { CvtSeg s[12]; int off[13]; int total8; };

__global__ void cvt_f2h(CvtCfg cfg)
{
    int i = blockIdx.x*blockDim.x + threadIdx.x;
    if (i >= cfg.total8) return;
    int lo = 0;
    #pragma unroll
    for (int k=1;k<=12;k++) if (i >= cfg.off[k]) lo = k;
    int j = i - cfg.off[lo];
    const float* src = cfg.s[lo].src;
    __half* dst = cfg.s[lo].dst;
    int cpr = cfg.s[lo].cpr, drc = cfg.s[lo].drc, doff = cfg.s[lo].doff;
    int row = j / cpr;
    int col = j - row*cpr;
    size_t dchunk = (size_t)row*drc + doff + col;
    const float4* sp = (const float4*)src + 2*(size_t)j;
    float4 u = sp[0], v = sp[1];
    __half2 h0 = __floats2half2_rn(u.x,u.y), h1 = __floats2half2_rn(u.z,u.w);
    __half2 h2 = __floats2half2_rn(v.x,v.y), h3 = __floats2half2_rn(v.z,v.w);
    uint4 o;
    o.x = *(uint32_t*)&h0; o.y = *(uint32_t*)&h1;
    o.z = *(uint32_t*)&h2; o.w = *(uint32_t*)&h3;
    *((uint4*)(dst + 8*dchunk)) = o;
}

// =====================  fp16 tensor-core GEMM (cp.async, 3-stage, BK=64) ====
// C[M,N] = A[M,K] @ W[N,K]^T + bias (+bias2)   [R14 config — best measured]
// BM=128, BN=64, BK=64(halves). 256 threads, 8 warps (4m x 2n), warp 32x32.

__device__ __forceinline__ void issue_stage(const __half* A, int lda,
                                            const __half* W, int ldw,
                                            int bm, int bn, int t, int k0,
                                            uint32_t aBase, uint32_t bBase)
{
    const int r0 = t>>3, ch = t&7;   // 32 row-groups x 8 chunks
    #pragma unroll
    for (int j=0;j<4;j++){
        int row = r0 + 32*j;
        const __half* a = A + (size_t)(bm+row)*lda + k0 + ch*8;
        uint32_t d = aBase + 4*((row<<5) + ((ch ^ (row&7))<<2));
        asm volatile("cp.async.cg.shared.global [%0], [%1], 16;\n" :: "r"(d), "l"(a) : "memory");
    }
    #pragma unroll
    for (int j=0;j<2;j++){
        int row = r0 + 32*j;
        const __half* b = W + (size_t)(bn+row)*ldw + k0 + ch*8;
        uint32_t d = bBase + 4*((row<<5) + ((ch ^ (row&7))<<2));
        asm volatile("cp.async.cg.shared.global [%0], [%1], 16;\n" :: "r"(d), "l"(b) : "memory");
    }
}

__device__ __forceinline__ void ldm_x4(uint32_t& r0, uint32_t& r1, uint32_t& r2, uint32_t& r3,
                                       uint32_t addr){
    asm volatile("ldmatrix.sync.aligned.m8n8.x4.shared.b16 {%0,%1,%2,%3}, [%4];"
        : "=r"(r0), "=r"(r1), "=r"(r2), "=r"(r3) : "r"(addr));
}

// smem layout (bytes): A stages 3x16384 @0, B stages 3x8192 @49152. total 73728.
__global__ void __launch_bounds__(256,3) gemm_f16(
    const __half* __restrict__ A, int lda,
    const __half* __restrict__ W, int ldw, int S,     // S = K/64 stages
    const float* __restrict__ b0, const float* __restrict__ b1,
    const float* __restrict__ b2, const float* __restrict__ b3,
    const float* __restrict__ e0, const float* __restrict__ e1,
    const float* __restrict__ e2, const float* __restrict__ e3,
    int has2, float* __restrict__ C, int ldc)
{
    extern __shared__ __align__(16) uint32_t sm[];
    const int tid = threadIdx.x;
    const int wid = tid>>5, lane = tid&31;
    const int bm = blockIdx.y*128, bn = blockIdx.x*64;
    const int wm = (wid>>1)*32, wn = (wid&1)*32;
    const int g = lane>>2, tig = lane&3;
    const int grp = lane>>3, rowin = lane&7;

    const uint32_t smBase = (uint32_t)__cvta_generic_to_shared(&sm[0]);

    float acc[2][4][4];
    #pragma unroll
    for (int i=0;i<2;i++)
        #pragma unroll
        for (int j=0;j<4;j++)
            #pragma unroll
            for (int t=0;t<4;t++) acc[i][j][t]=0.f;

    issue_stage(A, lda, W, ldw, bm, bn, tid, 0,  smBase,         smBase+49152);
    asm volatile("cp.async.commit_group;\n" ::: "memory");
    issue_stage(A, lda, W, ldw, bm, bn, tid, 64, smBase+16384,   smBase+49152+8192);
    asm volatile("cp.async.commit_group;\n" ::: "memory");

    for (int s = 0; s < S; s++){
        if (s+1 < S) asm volatile("cp.async.wait_group 1;\n" ::: "memory");
        else         asm volatile("cp.async.wait_group 0;\n" ::: "memory");
        __syncthreads();

        if (s+2 < S){
            int b2i = (s+2)%3;
            issue_stage(A, lda, W, ldw, bm, bn, tid, (s+2)*64,
                        smBase + b2i*16384, smBase + 49152 + b2i*8192);
            asm volatile("cp.async.commit_group;\n" ::: "memory");
        }

        const int buf = s%3;
        const uint32_t aBase = smBase + buf*16384;
        const uint32_t bBase = smBase + 49152 + buf*8192;

        #pragma unroll
        for (int kk=0;kk<4;kk++){
            uint32_t af[2][4], bf[2][4];
            #pragma unroll
            for (int mf=0;mf<2;mf++){
                int arow  = wm + mf*16 + ((grp&1)<<3) + rowin;
                int achunk = kk*2 + (grp>>1);
                uint32_t aw = (arow<<5) + ((achunk ^ (arow&7))<<2);
                ldm_x4(af[mf][0], af[mf][1], af[mf][2], af[mf][3], aBase + 4*aw);
            }
            #pragma unroll
            for (int nf2=0;nf2<2;nf2++){
                int brow  = wn + nf2*16 + ((grp>>1)<<3) + rowin;
                int bchunk = kk*2 + (grp&1);
                uint32_t bw = (brow<<5) + ((bchunk ^ (brow&7))<<2);
                ldm_x4(bf[nf2][0], bf[nf2][1], bf[nf2][2], bf[nf2][3], bBase + 4*bw);
            }
            #pragma unroll
            for (int mf=0;mf<2;mf++)
                #pragma unroll
                for (int nf=0;nf<4;nf++)
                    asm volatile(
                        "mma.sync.aligned.m16n8k16.row.col.f32.f16.f16.f32 "
                        "{%0,%1,%2,%3},{%4,%5,%6,%7},{%8,%9},{%0,%1,%2,%3};"
                        : "+f"(acc[mf][nf][0]), "+f"(acc[mf][nf][1]),
                          "+f"(acc[mf][nf][2]), "+f"(acc[mf][nf][3])
                        : "r"(af[mf][0]), "r"(af[mf][1]), "r"(af[mf][2]), "r"(af[mf][3]),
                          "r"(bf[nf>>1][(nf&1)*2]), "r"(bf[nf>>1][(nf&1)*2+1]));
        }
    }

    // epilogue (bias quartered by 1024-col blocks)
    const int q = bn>>10;
    const float* bq = (q==0)?b0:(q==1)?b1:(q==2)?b2:b3;
    const float* eq = (q==0)?e0:(q==1)?e1:(q==2)?e2:e3;
    #pragma unroll
    for (int mf=0;mf<2;mf++){
        int row = bm + wm + mf*16 + g;
        #pragma unroll
        for (int nf=0;nf<4;nf++){
            int col = bn + wn + nf*8 + 2*tig;
            int cq = col & 1023;
            float b0v = bq[cq], b1v = bq[cq+1];
            if (has2){ b0v += eq[cq]; b1v += eq[cq+1]; }
            float2 v0; v0.x = acc[mf][nf][0] + b0v; v0.y = acc[mf][nf][1] + b1v;
            float2 v1; v1.x = acc[mf][nf][2] + b0v; v1.y = acc[mf][nf][3] + b1v;
            *(float2*)&C[(size_t)row*ldc + col]     = v0;
            *(float2*)&C[(size_t)(row+8)*ldc + col] = v1;
        }
    }
}

// ---------------- LSTM pointwise (gate order i,f,g,o) ----------------------
__global__ void lstm_pw(const float* __restrict__ g, const float* __restrict__ cprev,
                        float* __restrict__ hout, float* __restrict__ cout,
                        __half* __restrict__ hout16, int ldh)
{
    int idx = blockIdx.x*blockDim.x + threadIdx.x;
    if (idx >= BSZ*CD) return;
    int bb = idx >> 10, cc = idx & 1023;
    const float* gr = g + (size_t)bb*4096;
    float gi = sigf(gr[cc]);
    float gf = sigf(gr[1024+cc]);
    float gg = tanhfast(gr[2048+cc]);
    float go = sigf(gr[3072+cc]);
    float cn = gf*cprev[idx] + gi*gg;
    cout[idx] = cn;
    float h = go * tanhfast(cn);
    hout[idx] = h;
    hout16[(size_t)bb*ldh + cc] = __float2half(h);
}

// ---------------- fused small heads (fp16 h input) ---------------------------
__global__ void gemv_heads4(const __half* __restrict__ h,
                            const float* __restrict__ Wrb, const float* __restrict__ brb,
                            const float* __restrict__ Wwb, const float* __restrict__ bwb,
                            const float* __restrict__ Wsh, const float* __restrict__ bsh,
                            const float* __restrict__ Wga, const float* __restrict__ bga,
                            float* __restrict__ orb, float* __restrict__ owb,
                            float* __restrict__ osh, float* __restrict__ oga)
{
    int gw = (blockIdx.x*blockDim.x + threadIdx.x) >> 5;
    int lane = threadIdx.x & 31;
    if (gw >= BSZ*48) return;
    int bidx = gw / 48, t = gw - bidx*48;
    const float* W; const float* bias; float* out; int n; int nout;
    if (t < 8)       { W=Wrb; bias=brb; out=orb; n=t;     nout=8;  }
    else if (t < 16) { W=Wwb; bias=bwb; out=owb; n=t-8;   nout=8;  }
    else if (t < 40) { W=Wsh; bias=bsh; out=osh; n=t-16;  nout=24; }
    else             { W=Wga; bias=bga; out=oga; n=t-40;  nout=8;  }
    const uint2* hv = (const uint2*)(h + (size_t)bidx*CD);
    const float4* wv = (const float4*)(W + (size_t)n*CD);
    float s = 0.f;
    #pragma unroll 4
    for (int i=lane; i<CD/4; i+=32){
        uint2 u = hv[i];
        float2 f0 = __half22float2(*(__half2*)&u.x);
        float2 f1 = __half22float2(*(__half2*)&u.y);
        float4 w = wv[i];
        s += f0.x*w.x + f0.y*w.y + f1.x*w.z + f1.y*w.w;
    }
    #pragma unroll
    for (int o=16;o;o>>=1) s += __shfl_xor_sync(0xffffffffu, s, o);
    if (lane==0) out[(size_t)bidx*nout + n] = s + bias[n];
}

// ---------------- fused NTM tail: write path + read path --------------------
// One CTA per batch. Phase W: w_w content softmax on M_prev + memory update.
// Phase R: w_r content softmax on Mo (L1-hot) + shift + sharpen + r.
__global__ void __launch_bounds__(256) ntm_tail(
    const float* __restrict__ Mp,
    const float* __restrict__ heads, int ldk,    // RK@0 WK@1024 ER@2048 AD@3072
    const float* __restrict__ bwraw, const float* __restrict__ brraw,
    const float* __restrict__ shraw, const float* __restrict__ garaw,
    float* __restrict__ Mo, float* __restrict__ wout, float* __restrict__ rout)
{
    int b = blockIdx.x;
    __shared__ __align__(16) float Kn[HH][DD];
    __shared__ float cosm[HH][ND];
    __shared__ float inv[HH];
    __shared__ float s3[HH][3];
    __shared__ float er[HH][DD], ad[HH][DD];
    __shared__ float part[HH][2][DD];
    int tid = threadIdx.x, wid = tid>>5, lane = tid&31;
    const int d = tid & 127, half = tid >> 7;

    // ===================== phase W =====================
    const float* hb = heads + (size_t)b*ldk;
    for (int i=tid; i<HH*DD; i+=256){
        Kn[i>>7][i&127] = hb[1024 + i];              // WK
        er[i>>7][i&127] = sigf(hb[2048 + i]);        // erase
        ad[i>>7][i&127] = tanhfast(hb[3072 + i]);    // add
    }
    __syncthreads();
    {
        float s=0.f;
        for (int dd=lane; dd<DD; dd+=32){ float v=Kn[wid][dd]; s+=v*v; }
        #pragma unroll
        for (int o=16;o;o>>=1) s += __shfl_xor_sync(0xffffffffu, s, o);
        if (lane==0) inv[wid] = 1.f / fmaxf(sqrtf(s), 1e-12f);
    }
    __syncthreads();
    for (int i=tid; i<HH*DD; i+=256) Kn[i>>7][i&127] *= inv[i>>7];
    __syncthreads();

    for (int n = wid; n < ND; n += 8) {
        const float4* Mr = (const float4*)(Mp + ((size_t)b*ND + n)*DD);
        float4 mv = Mr[lane];
        float vals[9];
        vals[8] = mv.x*mv.x + mv.y*mv.y + mv.z*mv.z + mv.w*mv.w;
        #pragma unroll
        for (int h=0;h<HH;h++){
            float4 kv = *(const float4*)&Kn[h][lane*4];
            vals[h] = mv.x*kv.x + mv.y*kv.y + mv.z*kv.z + mv.w*kv.w;
        }
        #pragma unroll
        for (int o=16;o;o>>=1)
            #pragma unroll
            for (int j=0;j<9;j++) vals[j] += __shfl_xor_sync(0xffffffffu, vals[j], o);
        if (lane==0){
            float im = 1.f / fmaxf(sqrtf(vals[8]), 1e-12f);
            #pragma unroll
            for (int h=0;h<HH;h++) cosm[h][n] = vals[h]*im;
        }
    }
    __syncthreads();

    {
        float beta = softplusf_(bwraw[(size_t)b*HH + wid]);
        float mx = -1e30f;
        #pragma unroll
        for (int k=0;k<8;k++) mx = fmaxf(mx, beta*cosm[wid][lane+32*k]);
        #pragma unroll
        for (int o=16;o;o>>=1) mx = fmaxf(mx, __shfl_xor_sync(0xffffffffu, mx, o));
        float ev[8]; float sum=0.f;
        #pragma unroll
        for (int k=0;k<8;k++){ float e = expf(beta*cosm[wid][lane+32*k]-mx); ev[k]=e; sum+=e; }
        #pragma unroll
        for (int o=16;o;o>>=1) sum += __shfl_xor_sync(0xffffffffu, sum, o);
        float isum = 1.f/sum;
        #pragma unroll
        for (int k=0;k<8;k++) cosm[wid][lane+32*k] = ev[k]*isum;
    }
    __syncthreads();

    for (int n = half; n < ND; n += 2){
        size_t off = ((size_t)b*ND + n)*DD + d;
        float mp = Mp[off];
        float es=0.f, as=0.f;
        #pragma unroll
        for (int h=0;h<HH;h++){
            float w = cosm[h][n];
            es += w*er[h][d];
            as += w*ad[h][d];
        }
        Mo[off] = mp*(1.f-es) + as;
    }
    __syncthreads();   // Mo writes visible to all threads of this CTA

    // ===================== phase R =====================
    for (int i=tid; i<HH*DD; i+=256) Kn[i>>7][i&127] = hb[i];  // RK
    __syncthreads();
    {
        float s=0.f;
        for (int dd=lane; dd<DD; dd+=32){ float v=Kn[wid][dd]; s+=v*v; }
        #pragma unroll
        for (int o=16;o;o>>=1) s += __shfl_xor_sync(0xffffffffu, s, o);
        if (lane==0) inv[wid] = 1.f / fmaxf(sqrtf(s), 1e-12f);
    }
    __syncthreads();
    for (int i=tid; i<HH*DD; i+=256) Kn[i>>7][i&127] *= inv[i>>7];
    __syncthreads();

    for (int n = wid; n < ND; n += 8) {
        const float4* Mr = (const float4*)(Mo + ((size_t)b*ND + n)*DD);
        float4 mv = Mr[lane];
        float vals[9];
        vals[8] = mv.x*mv.x + mv.y*mv.y + mv.z*mv.z + mv.w*mv.w;
        #pragma unroll
        for (int h=0;h<HH;h++){
            float4 kv = *(const float4*)&Kn[h][lane*4];
            vals[h] = mv.x*kv.x + mv.y*kv.y + mv.z*kv.z + mv.w*kv.w;
        }
        #pragma unroll
        for (int o=16;o;o>>=1)
            #pragma unroll
            for (int j=0;j<9;j++) vals[j] += __shfl_xor_sync(0xffffffffu, vals[j], o);
        if (lane==0){
            float im = 1.f / fmaxf(sqrtf(vals[8]), 1e-12f);
            #pragma unroll
            for (int h=0;h<HH;h++) cosm[h][n] = vals[h]*im;
        }
    }
    __syncthreads();

    float beta = softplusf_(brraw[(size_t)b*HH + wid]);
    float mx = -1e30f;
    #pragma unroll
    for (int k=0;k<8;k++) mx = fmaxf(mx, beta*cosm[wid][lane+32*k]);
    #pragma unroll
    for (int o=16;o;o>>=1) mx = fmaxf(mx, __shfl_xor_sync(0xffffffffu, mx, o));
    float ev[8]; float sum=0.f;
    #pragma unroll
    for (int k=0;k<8;k++){ float e = expf(beta*cosm[wid][lane+32*k]-mx); ev[k]=e; sum+=e; }
    #pragma unroll
    for (int o=16;o;o>>=1) sum += __shfl_xor_sync(0xffffffffu, sum, o);
    float isum = 1.f/sum;
    __syncthreads();
    #pragma unroll
    for (int k=0;k<8;k++) cosm[wid][lane+32*k] = ev[k]*isum;

    if (lane==0){
        const float* sr = shraw + ((size_t)b*HH + wid)*3;
        float a=sr[0], bb2=sr[1], cc=sr[2];
        float m = fmaxf(a, fmaxf(bb2, cc));
        float ea=expf(a-m), eb=expf(bb2-m), ec=expf(cc-m);
        float is = 1.f/(ea+eb+ec);
        s3[wid][0]=ea*is; s3[wid][1]=eb*is; s3[wid][2]=ec*is;
    }
    __syncthreads();

    float sh0 = s3[wid][0], sh1 = s3[wid][1], sh2 = s3[wid][2];
    float gexp = 1.f + softplusf_(garaw[(size_t)b*HH + wid]);
    float wg[8]; float sum2=0.f;
    #pragma unroll
    for (int k=0;k<8;k++){
        int n = lane+32*k;
        float wsv = sh0*cosm[wid][(n+1)&255] + sh1*cosm[wid][n] + sh2*cosm[wid][(n-1)&255];
        float p = powf(wsv, gexp);
        wg[k]=p; sum2+=p;
    }
    #pragma unroll
    for (int o=16;o;o>>=1) sum2 += __shfl_xor_sync(0xffffffffu, sum2, o);
    float inv2 = 1.f/(sum2+1e-12f);
    __syncthreads();   // all shift reads of cosm done before overwrite
    #pragma unroll
    for (int k=0;k<8;k++){
        float w = wg[k]*inv2;
        cosm[wid][lane+32*k] = w;
        wout[((size_t)b*HH+wid)*ND + lane+32*k] = w;
    }
    __syncthreads();

    float accv[HH];
    #pragma unroll
    for (int h=0;h<HH;h++) accv[h]=0.f;
    for (int n = half; n < ND; n += 2){
        float m = Mo[((size_t)b*ND + n)*DD + d];
        #pragma unroll
        for (int h=0;h<HH;h++) accv[h] += cosm[h][n]*m;
    }
    #pragma unroll
    for (int h=0;h<HH;h++) part[h][half][d] = accv[h];
    __syncthreads();
    for (int i=tid; i<HH*DD; i+=256){
        int h = i>>7, dd = i&127;
        rout[((size_t)b*HH+h)*DD + dd] = part[h][0][dd] + part[h][1][dd];
    }
}

// ---------------- launcher ---------------------------------------------------
extern "C" void kernel_launch(void* const* d_in, const int* in_sizes, int n_in,
                              void* d_out, int out_size)
{
    const float* x      = (const float*)d_in[0];
    const float* h1     = (const float*)d_in[1];
    const float* c1     = (const float*)d_in[2];
    const float* h2     = (const float*)d_in[3];
    const float* c2     = (const float*)d_in[4];
    const float* r_prev = (const float*)d_in[6];
    const float* M_prev = (const float*)d_in[7];
    const float* W_ih1  = (const float*)d_in[8];
    const float* W_hh1  = (const float*)d_in[9];
    const float* b_ih1  = (const float*)d_in[10];
    const float* b_hh1  = (const float*)d_in[11];
    const float* W_ih2  = (const float*)d_in[12];
    const float* W_hh2  = (const float*)d_in[13];
    const float* b_ih2  = (const float*)d_in[14];
    const float* b_hh2  = (const float*)d_in[15];
    const float* W_rk   = (const float*)d_in[16];
    const float* b_rk   = (const float*)d_in[17];
    const float* W_wk   = (const float*)d_in[18];
    const float* b_wk   = (const float*)d_in[19];
    const float* W_rb   = (const float*)d_in[20];
    const float* b_rb   = (const float*)d_in[21];
    const float* W_wb   = (const float*)d_in[22];
    const float* b_wb   = (const float*)d_in[23];
    const float* W_er   = (const float*)d_in[24];
    const float* b_er   = (const float*)d_in[25];
    const float* W_ad   = (const float*)d_in[26];
    const float* b_ad   = (const float*)d_in[27];
    const float* W_sh   = (const float*)d_in[28];
    const float* b_sh   = (const float*)d_in[29];
    const float* W_ga   = (const float*)d_in[30];
    const float* b_ga   = (const float*)d_in[31];

    float* out = (float*)d_out;
    const size_t HC = (size_t)BSZ*CD;
    float* h1n = out;
    float* c1n = out + HC;
    float* h2n = out + 2*HC;
    float* c2n = out + 3*HC;
    float* wr  = out + 4*HC;
    float* rr  = wr + (size_t)BSZ*HH*ND;
    float* Mo  = rr + (size_t)BSZ*HH*DD;

    float* S = nullptr;
    cudaGetSymbolAddress((void**)&S, g_scratch);
    float* gates = S + GATES_OFF;
    float* heads = S + HEADS_OFF;
    float* BR    = S + BR_OFF;
    float* BW    = S + BW_OFF;
    float* SHm   = S + SH_OFF;
    float* GA    = S + GA_OFF;
    __half* Hh   = (__half*)(S + FP16_OFF);

    const int DSMEM = 73728;
    cudaFuncSetAttribute(gemm_f16, cudaFuncAttributeMaxDynamicSharedMemorySize, DSMEM);

    // 0) batched f32->f16 conversion + concat gather
    {
        CvtCfg c{};
        struct Row { const float* s; unsigned d; int n8, cpr, drc, doff; };
        const Row rows[12] = {
            { W_ih1, WCAT1_H,            786432, 192, 320, 0   },
            { W_hh1, WCAT1_H,            524288, 128, 320, 192 },
            { W_ih2, WCAT2_H,            524288, 128, 256, 0   },
            { W_hh2, WCAT2_H,            524288, 128, 256, 128 },
            { W_rk,  WHD_H,              131072, 128, 128, 0   },
            { W_wk,  WHD_H + 1048576u,   131072, 128, 128, 0   },
            { W_er,  WHD_H + 2097152u,   131072, 128, 128, 0   },
            { W_ad,  WHD_H + 3145728u,   131072, 128, 128, 0   },
            { x,     ACAT1_H,             32768,  64, 320, 0   },
            { r_prev,ACAT1_H,             65536, 128, 320, 64  },
            { h1,    ACAT1_H,             65536, 128, 320, 192 },
            { h2,    ACAT2_H,             65536, 128, 256, 128 },
        };
        int acc = 0;
        for (int i=0;i<12;i++){
            c.s[i].src = rows[i].s;
            c.s[i].dst = Hh + rows[i].d;
            c.s[i].cpr = rows[i].cpr;
            c.s[i].drc = rows[i].drc;
            c.s[i].doff = rows[i].doff;
            c.off[i] = acc;
            acc += rows[i].n8;
        }
        c.off[12] = acc;
        c.total8 = acc;
        cvt_f2h<<<(c.total8 + 255)/256, 256>>>(c);
    }

    dim3 ggrid(4096/64, BSZ/128);   // 256 CTAs, 256 threads each

    // 1) LSTM1: gates = Acat1 @ Wcat1^T + b_ih1 + b_hh1
    gemm_f16<<<ggrid, 256, DSMEM>>>(Hh+ACAT1_H, 2560, Hh+WCAT1_H, 2560, 2560/64,
        b_ih1, b_ih1+1024, b_ih1+2048, b_ih1+3072,
        b_hh1, b_hh1+1024, b_hh1+2048, b_hh1+3072,
        1, gates, 4096);
    lstm_pw<<<(BSZ*CD + 255)/256, 256>>>(gates, c1, h1n, c1n, Hh+ACAT2_H, 2048);

    // 2) LSTM2
    gemm_f16<<<ggrid, 256, DSMEM>>>(Hh+ACAT2_H, 2048, Hh+WCAT2_H, 2048, 2048/64,
        b_ih2, b_ih2+1024, b_ih2+2048, b_ih2+3072,
        b_hh2, b_hh2+1024, b_hh2+2048, b_hh2+3072,
        1, gates, 4096);
    lstm_pw<<<(BSZ*CD + 255)/256, 256>>>(gates, c2, h2n, c2n, Hh+H2NH, 1024);

    // 3) fused head projections: heads = RK|WK|ER|AD
    gemm_f16<<<ggrid, 256, DSMEM>>>(Hh+H2NH, 1024, Hh+WHD_H, 1024, 1024/64,
        b_rk, b_wk, b_er, b_ad,
        nullptr, nullptr, nullptr, nullptr,
        0, heads, 4096);

    // 4) fused small heads (fp16 h input)
    gemv_heads4<<<(BSZ*48*32 + 255)/256, 256>>>(Hh+H2NH,
        W_rb, b_rb, W_wb, b_wb, W_sh, b_sh, W_ga, b_ga,
        BR, BW, SHm, GA);

    // 5) fused NTM tail (write path + read path in one kernel)
    ntm_tail<<<BSZ, 256>>>(M_prev, heads, 4096, BW, BR, SHm, GA, Mo, wr, rr);
}